// round 16
// baseline (speedup 1.0000x reference)
#include <cuda_runtime.h>
#include <cuda_fp16.h>
#include <math.h>
#include <stdint.h>

// ---------------------------------------------------------------------------
// Problem constants
// ---------------------------------------------------------------------------
#define NN    299593      // total nodes, complete 8-ary tree, 7 levels
#define HH    128         // D_ENC == D_EMB
#define NIOU  384         // 3*H
#define DDEC  256
#define NPAR  37449       // nodes at levels 0..5 (all parents)

#define CHUNK_BYTES 8192  // one pre-swizzled B chunk: 32 N-rows x 128 K x fp16
#define CHUNK_U4    (CHUNK_BYTES / 16)

// Scratch (device globals: allocation-free per harness rules)
__device__ float g_h [(size_t)NN  * HH];
__device__ float g_c [(size_t)NN  * HH];
__device__ float g_xf[(size_t)NPAR * HH];
__device__ float g_uh[(size_t)NPAR * NIOU];
__device__ float g_fc[(size_t)NPAR * HH];

// Pre-swizzled fp16 weight blobs (single-rounded), 32-row x 128-K chunks
__device__ uint4 g_Wiou_sw[12 * CHUNK_U4];
__device__ uint4 g_U_sw   [16 * CHUNK_U4];  // [U_iou(384) | U_f(128)] cols
__device__ uint4 g_Wout_sw[ 8 * CHUNK_U4];

// ---------------------------------------------------------------------------
// Helpers
// ---------------------------------------------------------------------------
__device__ __forceinline__ uint32_t smem_to_u32(const void* p) {
    uint32_t a;
    asm("{ .reg .u64 t; cvta.to.shared.u64 t, %1; cvt.u32.u64 %0, t; }" : "=r"(a) : "l"(p));
    return a;
}
__device__ __forceinline__ uint32_t swz(uint32_t o) { return o ^ ((o >> 3) & 0x70); }
__device__ __forceinline__ uint32_t offA(int row, int k) {   // 128-row tile: 16 atoms/kblk
    return swz((uint32_t)(((row >> 3) + (k >> 6) * 16) * 1024 + (row & 7) * 128 + (k & 63) * 2));
}
__device__ __forceinline__ uint32_t offA64(int row, int k) { // 64-row tile: 8 atoms/kblk
    return swz((uint32_t)(((row >> 3) + (k >> 6) * 8) * 1024 + (row & 7) * 128 + (k & 63) * 2));
}
__device__ __forceinline__ uint32_t offA16(int row, int k) { // 16-row tile: 2 atoms/kblk
    return swz((uint32_t)(((row >> 3) + (k >> 6) * 2) * 1024 + (row & 7) * 128 + (k & 63) * 2));
}
__device__ __forceinline__ uint32_t offB32(int row, int k) { // 32-row tile: 4 atoms/kblk
    return swz((uint32_t)(((row >> 3) + (k >> 6) * 4) * 1024 + (row & 7) * 128 + (k & 63) * 2));
}
__device__ __forceinline__ uint32_t packh2(float a, float b) {
    __half2 h = __floats2half2_rn(a, b);
    return *reinterpret_cast<uint32_t*>(&h);
}
__device__ __forceinline__ float sigf(float v) {
    return __fdividef(1.0f, 1.0f + __expf(-v));
}
__device__ __forceinline__ float tanh_fast(float x) {
    float t = __expf(2.0f * x);
    return 1.0f - __fdividef(2.0f, t + 1.0f);
}

#define LDSM4(R0, R1, R2, R3, ADDR) \
    asm volatile("ldmatrix.sync.aligned.m8n8.x4.shared.b16 {%0,%1,%2,%3}, [%4];" \
                 : "=r"(R0), "=r"(R1), "=r"(R2), "=r"(R3) : "r"(ADDR))
#define LDSM2(R0, R1, ADDR) \
    asm volatile("ldmatrix.sync.aligned.m8n8.x2.shared.b16 {%0,%1}, [%2];" \
                 : "=r"(R0), "=r"(R1) : "r"(ADDR))

__device__ __forceinline__ void mma_f16(float (&d)[4], const uint32_t (&a)[4],
                                        uint32_t b0, uint32_t b1) {
    asm volatile("mma.sync.aligned.m16n8k16.row.col.f32.f16.f16.f32 "
                 "{%0,%1,%2,%3}, {%4,%5,%6,%7}, {%8,%9}, {%0,%1,%2,%3};"
                 : "+f"(d[0]), "+f"(d[1]), "+f"(d[2]), "+f"(d[3])
                 : "r"(a[0]), "r"(a[1]), "r"(a[2]), "r"(a[3]), "r"(b0), "r"(b1));
}

__device__ __forceinline__ void zacc(float (&a)[2][2][4]) {
#pragma unroll
    for (int i = 0; i < 2; i++)
#pragma unroll
        for (int j = 0; j < 2; j++)
#pragma unroll
            for (int k = 0; k < 4; k++) a[i][j][k] = 0.f;
}

// Single 32-col chunk: per-warp C[m32 x n16] += A[128x128] * B[32x128]^T
__device__ __forceinline__ void mma_chunk32(uint32_t Abase, uint32_t Bbase,
                                            float (&acc)[2][2][4],
                                            int wm, int wn, int lane) {
    int rA = wm * 32 + (lane & 15);
    uint32_t PA = Abase + ((rA >> 3) << 10) + ((rA & 7) << 7);
    uint32_t CA = (rA & 7) << 4;
    int aK = (lane >> 4) << 3;
    int nB = wn * 16 + (((lane >> 4) & 1) << 3) + (lane & 7);
    uint32_t PB = Bbase + ((nB >> 3) << 10) + ((nB & 7) << 7);
    uint32_t CB = (nB & 7) << 4;
    int bK = ((lane >> 3) & 1) << 3;
#pragma unroll
    for (int s = 0; s < 8; s++) {
        int kA = (s << 4) + aK;
        int kB = (s << 4) + bK;
        uint32_t aAh = PA + ((uint32_t)(kA >> 6) << 14) + ((uint32_t)((kA & 63) << 1) ^ CA);
        uint32_t aBh = PB + ((uint32_t)(kB >> 6) << 12) + ((uint32_t)((kB & 63) << 1) ^ CB);
        uint32_t ah0[4], ah1[4], bh[4];
        LDSM4(ah0[0], ah0[1], ah0[2], ah0[3], aAh);
        LDSM4(ah1[0], ah1[1], ah1[2], ah1[3], aAh + 2048);
        LDSM4(bh[0], bh[1], bh[2], bh[3], aBh);
        mma_f16(acc[0][0], ah0, bh[0], bh[1]);
        mma_f16(acc[1][0], ah1, bh[0], bh[1]);
        mma_f16(acc[0][1], ah0, bh[2], bh[3]);
        mma_f16(acc[1][1], ah1, bh[2], bh[3]);
    }
}

// Pair-fused: A fragments loaded once feed 2 B chunks
__device__ __forceinline__ void mma_pair32(uint32_t Abase, uint32_t B0, uint32_t B1,
                                           float (&aX)[2][2][4], float (&aY)[2][2][4],
                                           int wm, int wn, int lane) {
    int rA = wm * 32 + (lane & 15);
    uint32_t PA = Abase + ((rA >> 3) << 10) + ((rA & 7) << 7);
    uint32_t CA = (rA & 7) << 4;
    int aK = (lane >> 4) << 3;
    int nB = wn * 16 + (((lane >> 4) & 1) << 3) + (lane & 7);
    uint32_t SB = ((uint32_t)(nB >> 3) << 10) + ((uint32_t)(nB & 7) << 7);
    uint32_t CB = (nB & 7) << 4;
    int bK = ((lane >> 3) & 1) << 3;
#pragma unroll
    for (int s = 0; s < 8; s++) {
        int kA = (s << 4) + aK;
        int kB = (s << 4) + bK;
        uint32_t aAh = PA + ((uint32_t)(kA >> 6) << 14) + ((uint32_t)((kA & 63) << 1) ^ CA);
        uint32_t ob  = SB + ((uint32_t)(kB >> 6) << 12) + ((uint32_t)((kB & 63) << 1) ^ CB);
        uint32_t ah0[4], ah1[4], bX[4], bY[4];
        LDSM4(ah0[0], ah0[1], ah0[2], ah0[3], aAh);
        LDSM4(ah1[0], ah1[1], ah1[2], ah1[3], aAh + 2048);
        LDSM4(bX[0], bX[1], bX[2], bX[3], B0 + ob);
        LDSM4(bY[0], bY[1], bY[2], bY[3], B1 + ob);
        mma_f16(aX[0][0], ah0, bX[0], bX[1]);
        mma_f16(aX[1][0], ah1, bX[0], bX[1]);
        mma_f16(aX[0][1], ah0, bX[2], bX[3]);
        mma_f16(aX[1][1], ah1, bX[2], bX[3]);
        mma_f16(aY[0][0], ah0, bY[0], bY[1]);
        mma_f16(aY[1][0], ah1, bY[0], bY[1]);
        mma_f16(aY[0][1], ah0, bY[2], bY[3]);
        mma_f16(aY[1][1], ah1, bY[2], bY[3]);
    }
}

// Out kernel: 64-row tile, 4 B chunks share A fragments; per-warp n8 per chunk
__device__ __forceinline__ void mma_quad64(uint32_t Abase, uint32_t Bbase,
                                           float (*acc)[2][4],   // [4][2][4]
                                           int wm, int wn, int lane) {
    int rA = wm * 32 + (lane & 15);
    uint32_t PA = Abase + ((rA >> 3) << 10) + ((rA & 7) << 7);
    uint32_t CA = (rA & 7) << 4;
    int aK = (lane >> 4) << 3;
    int nB = wn * 8 + (lane & 7);
    uint32_t SB = ((uint32_t)(nB >> 3) << 10) + ((uint32_t)(nB & 7) << 7);
    uint32_t CB = (nB & 7) << 4;
    int bK = ((lane >> 3) & 1) << 3;
#pragma unroll
    for (int s = 0; s < 8; s++) {
        int kA = (s << 4) + aK;
        int kB = (s << 4) + bK;
        uint32_t aAh = PA + ((uint32_t)(kA >> 6) << 13) + ((uint32_t)((kA & 63) << 1) ^ CA);
        uint32_t ob  = SB + ((uint32_t)(kB >> 6) << 12) + ((uint32_t)((kB & 63) << 1) ^ CB);
        uint32_t ah0[4], ah1[4];
        LDSM4(ah0[0], ah0[1], ah0[2], ah0[3], aAh);
        LDSM4(ah1[0], ah1[1], ah1[2], ah1[3], aAh + 2048);
#pragma unroll
        for (int j = 0; j < 4; j++) {
            uint32_t b0, b1;
            LDSM2(b0, b1, Bbase + (uint32_t)j * CHUNK_BYTES + ob);
            mma_f16(acc[j][0], ah0, b0, b1);
            mma_f16(acc[j][1], ah1, b0, b1);
        }
    }
}

// ---------------------------------------------------------------------------
// cp.async: one 8KB chunk, 256 threads x 2 x 16B, one commit group
// ---------------------------------------------------------------------------
__device__ __forceinline__ void cp_chunk(uint32_t dst, const uint4* src, int t) {
    const char* s = (const char*)src;
#pragma unroll
    for (int i = 0; i < 2; i++)
        asm volatile("cp.async.cg.shared.global [%0], [%1], 16;"
                     :: "r"(dst + (uint32_t)(t * 16 + i * 4096)),
                        "l"(s + t * 16 + i * 4096) : "memory");
    asm volatile("cp.async.commit_group;" ::: "memory");
}
#define CP_WAIT0() asm volatile("cp.async.wait_group 0;" ::: "memory")

// ---------------------------------------------------------------------------
// Weight prep (single launch): fp16 round + swizzle all four blobs
// ---------------------------------------------------------------------------
__global__ void prep_all(const float* __restrict__ W_iou, const float* __restrict__ U_iou,
                         const float* __restrict__ U_f, const float* __restrict__ W_out) {
    int b = blockIdx.x;
    const float* src; int ncols, dst_id, chunkoff, rel;
    if (b < 192)      { src = W_iou; ncols = 384; dst_id = 0; chunkoff = 0;  rel = b; }
    else if (b < 384) { src = U_iou; ncols = 384; dst_id = 1; chunkoff = 0;  rel = b - 192; }
    else if (b < 448) { src = U_f;   ncols = 128; dst_id = 1; chunkoff = 12; rel = b - 384; }
    else              { src = W_out; ncols = 256; dst_id = 2; chunkoff = 0;  rel = b - 448; }
    int idx = rel * 256 + threadIdx.x;
    if (idx >= 128 * ncols) return;
    int k = idx / ncols, n = idx - k * ncols;
    float v = src[k * ncols + n];
    unsigned short hu = __half_as_ushort(__float2half_rn(v));
    unsigned char* bb = (dst_id == 0) ? (unsigned char*)g_Wiou_sw
                      : (dst_id == 1) ? (unsigned char*)g_U_sw
                                      : (unsigned char*)g_Wout_sw;
    unsigned char* blob = bb + (size_t)(chunkoff + (n >> 5)) * CHUNK_BYTES;
    int row = n & 31;
    *(unsigned short*)(blob + offB32(row, k)) = hu;
}

// ---------------------------------------------------------------------------
// Level SMEM (occ 3, 68KB): A [0,32768) | A2 [32768,36864) | ring 4x8KB
// Out SMEM: A64 [0,16384) | ring 8x8KB [16384,81920) | part [81920,83968)
// ---------------------------------------------------------------------------
#define SM_A2    32768
#define SM_B     36864
#define SM_LVL   69632
#define SM_OB    16384
#define SM_OPART 81920
#define SM_OUT   83968

// build a 128x128 fp16 tile from fp32 rows (src row-major, HH cols)
__device__ __forceinline__ void build_tile(char* Ac, const float* src, size_t base,
                                           int n_rows, int t) {
    int row = t >> 1, kh = (t & 1) << 6;
    bool val = row < n_rows;
    const float4* xr = (const float4*)(src + (base + row) * HH + kh);
#pragma unroll
    for (int gg = 0; gg < 8; gg++) {
        float v[8];
        if (val) {
            float4 a = xr[gg * 2], b = xr[gg * 2 + 1];
            v[0]=a.x; v[1]=a.y; v[2]=a.z; v[3]=a.w; v[4]=b.x; v[5]=b.y; v[6]=b.z; v[7]=b.w;
        } else {
#pragma unroll
            for (int q = 0; q < 8; q++) v[q] = 0.f;
        }
        *(uint4*)(Ac + offA(row, kh + gg * 8)) =
            make_uint4(packh2(v[0], v[1]), packh2(v[2], v[3]),
                       packh2(v[4], v[5]), packh2(v[6], v[7]));
    }
}

// 64-row variant (4 threads per row, 32 K each)
__device__ __forceinline__ void build_tile64(char* Ac, const float* src, size_t base,
                                             int n_rows, int t) {
    int row = t >> 2, kh = (t & 3) << 5;
    bool val = row < n_rows;
    const float4* xr = (const float4*)(src + (base + row) * HH + kh);
#pragma unroll
    for (int gg = 0; gg < 4; gg++) {
        float v[8];
        if (val) {
            float4 a = xr[gg * 2], b = xr[gg * 2 + 1];
            v[0]=a.x; v[1]=a.y; v[2]=a.z; v[3]=a.w; v[4]=b.x; v[5]=b.y; v[6]=b.z; v[7]=b.w;
        } else {
#pragma unroll
            for (int q = 0; q < 8; q++) v[q] = 0.f;
        }
        *(uint4*)(Ac + offA64(row, kh + gg * 8)) =
            make_uint4(packh2(v[0], v[1]), packh2(v[2], v[3]),
                       packh2(v[4], v[5]), packh2(v[6], v[7]));
    }
}

// chunk c -> blob source (0..11 GEMM1, 12..27 GEMM2)
__device__ __forceinline__ const uint4* lvl_src(int c) {
    if (c < 12) {
        int p = c / 3, sub = c - p * 3;              // blob chunk = sub*4 + p
        return g_Wiou_sw + (size_t)(sub * 4 + p) * CHUNK_U4;
    }
    return g_U_sw + (size_t)(c - 12) * CHUNK_U4;
}
// 16-step schedule: s<8 GEMM1 pairs (I,O)/(U); s>=8 pairs of 2
__device__ __forceinline__ int st_start(int s) {
    return (s < 8) ? s + ((s + 1) >> 1) : 12 + (s - 8) * 2;
}
__device__ __forceinline__ int st_cnt(int s) {
    return (s < 8) ? ((s & 1) ? 1 : 2) : 2;
}
__device__ __forceinline__ void issue_group(uint32_t sb, int s, int t) {
    int st = st_start(s), cn = st_cnt(s);
    uint32_t slot = (uint32_t)((s & 1) * 2);
    for (int j = 0; j < cn; j++)
        cp_chunk(sb + SM_B + (slot + j) * CHUNK_BYTES, lvl_src(st + j), t);
}

// ---------------------------------------------------------------------------
// Fused per-level kernel: one CTA per 128-row tile, 256 threads, 3 CTAs/SM
// ---------------------------------------------------------------------------
__global__ __launch_bounds__(256, 3)
void level_mm(const float* __restrict__ x, const float* __restrict__ b_iou,
              int base0, int n_total, int read_sums, int has_parent) {
    extern __shared__ __align__(1024) char smem[];
    uint32_t sb = smem_to_u32(smem);
    int t = threadIdx.x, lane = t & 31, w = t >> 5;
    int wm = w & 3, wn = w >> 2;
    int q = lane & 3, g = lane >> 2;
    int base = base0 + ((int)blockIdx.x << 7);
    int n_rows = n_total - ((int)blockIdx.x << 7); if (n_rows > 128) n_rows = 128;
    int pbase = (base - 1) >> 3;
    const int n_steps = has_parent ? 16 : 8;

    issue_group(sb, 0, t);
    build_tile(smem, x, (size_t)base, n_rows, t);

    float accI[2][2][4], accO[2][2][4], accU[2][2][4];
    zacc(accI); zacc(accO); zacc(accU);

    for (int s = 0; s < n_steps; s++) {
        CP_WAIT0();
        __syncthreads();               // group s landed; prior step's reads done
        if (s + 1 < n_steps) issue_group(sb, s + 1, t);
        uint32_t B0 = sb + SM_B + (uint32_t)((s & 1) * 2) * CHUNK_BYTES;

        if (s < 8) {
            if (!(s & 1)) {
                mma_pair32(sb, B0, B0 + CHUNK_BYTES, accI, accO, wm, wn, lane);
            } else {
                mma_chunk32(sb, B0, accU, wm, wn, lane);
                int p = s >> 1;
                // epilogue for pass p: gates -> c,h (global) + A2 sibling sums
#pragma unroll
                for (int mi = 0; mi < 2; mi++)
#pragma unroll
                for (int nn = 0; nn < 2; nn++) {
                    int cp = p * 32 + wn * 16 + nn * 8 + 2 * q;
                    float bi0 = __ldg(b_iou + cp),       bi1 = __ldg(b_iou + cp + 1);
                    float bo0 = __ldg(b_iou + 128 + cp), bo1 = __ldg(b_iou + 129 + cp);
                    float bu0 = __ldg(b_iou + 256 + cp), bu1 = __ldg(b_iou + 257 + cp);
#pragma unroll
                    for (int rh = 0; rh < 2; rh++) {
                        int lr = wm * 32 + mi * 16 + g + rh * 8;
                        int rg = base + lr;
                        bool val = lr < n_rows;
                        float2 ui = make_float2(0.f, 0.f), uo = ui, uu = ui, fc = ui;
                        if (val && read_sums) {
                            const float* uh = g_uh + (size_t)rg * NIOU + cp;
                            ui = *(const float2*)(uh);
                            uo = *(const float2*)(uh + 128);
                            uu = *(const float2*)(uh + 256);
                            fc = *(const float2*)(g_fc + (size_t)rg * HH + cp);
                        }
                        float c0 = sigf(accI[mi][nn][rh*2]   + bi0 + ui.x) *
                                   tanh_fast(accU[mi][nn][rh*2]   + bu0 + uu.x) + fc.x;
                        float c1 = sigf(accI[mi][nn][rh*2+1] + bi1 + ui.y) *
                                   tanh_fast(accU[mi][nn][rh*2+1] + bu1 + uu.y) + fc.y;
                        float h0 = sigf(accO[mi][nn][rh*2]   + bo0 + uo.x) * tanh_fast(c0);
                        float h1 = sigf(accO[mi][nn][rh*2+1] + bo1 + uo.y) * tanh_fast(c1);
                        if (val) {
                            *(float2*)(g_c + (size_t)rg * HH + cp) = make_float2(c0, c1);
                            *(float2*)(g_h + (size_t)rg * HH + cp) = make_float2(h0, h1);
                        }
                        if (has_parent) {
                            float hs0 = val ? h0 : 0.f, hs1 = val ? h1 : 0.f;
                            hs0 += __shfl_xor_sync(0xffffffffu, hs0, 4);
                            hs0 += __shfl_xor_sync(0xffffffffu, hs0, 8);
                            hs0 += __shfl_xor_sync(0xffffffffu, hs0, 16);
                            hs1 += __shfl_xor_sync(0xffffffffu, hs1, 4);
                            hs1 += __shfl_xor_sync(0xffffffffu, hs1, 8);
                            hs1 += __shfl_xor_sync(0xffffffffu, hs1, 16);
                            if (lane < 4) {
                                int row2 = 4 * wm + 2 * mi + rh;
                                *(uint32_t*)(smem + SM_A2 + offA16(row2, cp)) =
                                    packh2(hs0, hs1);
                            }
                        }
                    }
                }
                zacc(accI); zacc(accO); zacc(accU);
                if (s == 7 && has_parent) {
                    __syncthreads();           // all warps done reading A (GEMM1)
                    build_tile(smem, g_h, (size_t)base, n_rows, t);
                }
            }
        } else if (s < 14) {
            // two tiny GEMM2a chunks: Uh_sum[16 rows] = hsum @ U_iou
            int ch0 = (s - 8) * 2;
            if (w < 4) {
#pragma unroll
                for (int jj = 0; jj < 2; jj++) {
                    int ch = ch0 + jj;
                    uint32_t Bb = B0 + (uint32_t)jj * CHUNK_BYTES;
                    float acc2[4] = {0.f, 0.f, 0.f, 0.f};
                    int rA2 = lane & 15;
                    uint32_t PA2 = (sb + SM_A2) + ((uint32_t)(rA2 >> 3) << 10)
                                                + ((uint32_t)(rA2 & 7) << 7);
                    uint32_t CA2 = (rA2 & 7) << 4;
                    int aK = (lane >> 4) << 3;
                    int nB2 = w * 8 + (lane & 7);
                    uint32_t PB2 = Bb + ((uint32_t)(nB2 >> 3) << 10)
                                      + ((uint32_t)(nB2 & 7) << 7);
                    uint32_t CB2 = (nB2 & 7) << 4;
                    int kB2 = ((lane >> 3) & 1) << 3;
#pragma unroll
                    for (int ks = 0; ks < 8; ks++) {
                        int kA = (ks << 4) + aK;
                        int kB = (ks << 4) + kB2;
                        uint32_t aAh = PA2 + ((uint32_t)(kA >> 6) << 11)
                                           + (((uint32_t)(kA & 63) << 1) ^ CA2);
                        uint32_t aB  = PB2 + ((uint32_t)(kB >> 6) << 12)
                                           + (((uint32_t)(kB & 63) << 1) ^ CB2);
                        uint32_t a2h[4], b0, b1;
                        LDSM4(a2h[0], a2h[1], a2h[2], a2h[3], aAh);
                        LDSM2(b0, b1, aB);
                        mma_f16(acc2, a2h, b0, b1);
                    }
                    int cb2 = ch * 32 + w * 8 + 2 * (lane & 3);
                    int gr0 = lane >> 2;
                    if (gr0 * 8 < n_rows)
                        *(float2*)(g_uh + (size_t)(pbase + gr0) * NIOU + cb2) =
                            make_float2(acc2[0], acc2[1]);
                    if ((gr0 + 8) * 8 < n_rows)
                        *(float2*)(g_uh + (size_t)(pbase + gr0 + 8) * NIOU + cb2) =
                            make_float2(acc2[2], acc2[3]);
                }
            }
        } else {
            // GEMM2b pair: f = sigmoid(h@U_f + xf[par]); fc = f*c; reduce
            int cf0 = (s - 14) * 2;
            mma_pair32(sb, B0, B0 + CHUNK_BYTES, accI, accO, wm, wn, lane);
#pragma unroll
            for (int jj = 0; jj < 2; jj++) {
#pragma unroll
                for (int mi = 0; mi < 2; mi++)
#pragma unroll
                for (int nn = 0; nn < 2; nn++) {
                    int cfl = (cf0 + jj) * 32 + wn * 16 + nn * 8 + 2 * q;
                    float v[4];
#pragma unroll
                    for (int rh = 0; rh < 2; rh++) {
                        int lr = wm * 32 + mi * 16 + g + rh * 8;
                        int rg = base + lr;
                        float a0 = jj ? accO[mi][nn][rh*2]   : accI[mi][nn][rh*2];
                        float a1 = jj ? accO[mi][nn][rh*2+1] : accI[mi][nn][rh*2+1];
                        if (lr < n_rows) {
                            int pr = (rg - 1) >> 3;
                            float2 xf2 = *(const float2*)(g_xf + (size_t)pr * HH + cfl);
                            float2 c2  = *(const float2*)(g_c  + (size_t)rg * HH + cfl);
                            v[rh*2]   = sigf(a0 + xf2.x) * c2.x;
                            v[rh*2+1] = sigf(a1 + xf2.y) * c2.y;
                        } else { v[rh*2] = 0.f; v[rh*2+1] = 0.f; }
                    }
#pragma unroll
                    for (int rr = 0; rr < 4; rr++) {
                        float sv = v[rr];
                        sv += __shfl_xor_sync(0xffffffffu, sv, 4);
                        sv += __shfl_xor_sync(0xffffffffu, sv, 8);
                        sv += __shfl_xor_sync(0xffffffffu, sv, 16);
                        v[rr] = sv;
                    }
                    if (lane < 4) {
#pragma unroll
                        for (int rh = 0; rh < 2; rh++) {
                            int lr0 = wm * 32 + mi * 16 + rh * 8;
                            if (lr0 < n_rows) {
                                int pr = (base + lr0 - 1) >> 3;
                                *(float2*)(g_fc + (size_t)pr * HH + cfl) =
                                    make_float2(v[rh*2], v[rh*2+1]);
                            }
                        }
                    }
                }
            }
            zacc(accI); zacc(accO);
        }
    }
}

// ---------------------------------------------------------------------------
// Output kernel: 64-row tiles, occupancy 2, 2 quad-fused steps
// ---------------------------------------------------------------------------
__global__ __launch_bounds__(256, 2)
void out_mm(const float* __restrict__ b_out, const float* __restrict__ gamma,
            const float* __restrict__ beta, float* __restrict__ out) {
    extern __shared__ __align__(1024) char smem[];
    uint32_t sb = smem_to_u32(smem);
    int t = threadIdx.x, lane = t & 31, w = t >> 5;
    int wm = w & 1, wn = w >> 1;           // 2 x 4 warp grid
    int q = lane & 3, g = lane >> 2;
    int base = (int)blockIdx.x << 6;
    int n_rows = NN - base; if (n_rows > 64) n_rows = 64;

#pragma unroll
    for (int j = 0; j < 4; j++)
        cp_chunk(sb + SM_OB + (uint32_t)j * CHUNK_BYTES, g_Wout_sw + (size_t)j * CHUNK_U4, t);

    build_tile64(smem, g_h, (size_t)base, n_rows, t);

    float acc8[8][2][4];
#pragma unroll
    for (int c = 0; c < 8; c++)
#pragma unroll
        for (int i = 0; i < 2; i++)
#pragma unroll
            for (int k = 0; k < 4; k++) acc8[c][i][k] = 0.f;

    for (int s = 0; s < 2; s++) {
        CP_WAIT0();
        __syncthreads();
        if (s == 0) {
#pragma unroll
            for (int j = 0; j < 4; j++)
                cp_chunk(sb + SM_OB + (uint32_t)(4 + j) * CHUNK_BYTES,
                         g_Wout_sw + (size_t)(4 + j) * CHUNK_U4, t);
        }
        mma_quad64(sb, sb + SM_OB + (uint32_t)(s * 4) * CHUNK_BYTES,
                   &acc8[4 * s], wm, wn, lane);
    }

    // bias + per-row partial sums
    float s2[2][2] = {{0.f,0.f},{0.f,0.f}}, sq[2][2] = {{0.f,0.f},{0.f,0.f}};
#pragma unroll
    for (int ch = 0; ch < 8; ch++) {
        int cb = ch * 32 + wn * 8 + 2 * q;
        float b0 = __ldg(b_out + cb), b1 = __ldg(b_out + cb + 1);
#pragma unroll
        for (int mi = 0; mi < 2; mi++)
#pragma unroll
        for (int rh = 0; rh < 2; rh++) {
            float y0 = (acc8[ch][mi][rh*2]   += b0);
            float y1 = (acc8[ch][mi][rh*2+1] += b1);
            s2[mi][rh] += y0 + y1;
            sq[mi][rh] += y0 * y0 + y1 * y1;
        }
    }
#pragma unroll
    for (int mi = 0; mi < 2; mi++)
#pragma unroll
    for (int rh = 0; rh < 2; rh++) {
        s2[mi][rh] += __shfl_xor_sync(0xffffffffu, s2[mi][rh], 1);
        s2[mi][rh] += __shfl_xor_sync(0xffffffffu, s2[mi][rh], 2);
        sq[mi][rh] += __shfl_xor_sync(0xffffffffu, sq[mi][rh], 1);
        sq[mi][rh] += __shfl_xor_sync(0xffffffffu, sq[mi][rh], 2);
    }
    float2* part = (float2*)(smem + SM_OPART);   // [64][4]
    __syncthreads();
    if (q == 0) {
#pragma unroll
        for (int mi = 0; mi < 2; mi++)
#pragma unroll
        for (int rh = 0; rh < 2; rh++) {
            int lr = wm * 32 + mi * 16 + g + rh * 8;
            part[lr * 4 + wn] = make_float2(s2[mi][rh], sq[mi][rh]);
        }
    }
    __syncthreads();
    float mu[2][2], rs[2][2];
#pragma unroll
    for (int mi = 0; mi < 2; mi++)
#pragma unroll
    for (int rh = 0; rh < 2; rh++) {
        int lr = wm * 32 + mi * 16 + g + rh * 8;
        float ssum = 0.f, qsum = 0.f;
#pragma unroll
        for (int j = 0; j < 4; j++) {
            float2 p = part[lr * 4 + j];
            ssum += p.x; qsum += p.y;
        }
        float m = ssum * (1.f / 256.f);
        float var = qsum * (1.f / 256.f) - m * m;
        mu[mi][rh] = m;
        rs[mi][rh] = rsqrtf(var + 1e-5f);
    }
#pragma unroll
    for (int ch = 0; ch < 8; ch++) {
        int cb = ch * 32 + wn * 8 + 2 * q;
        float g0 = __ldg(gamma + cb), g1 = __ldg(gamma + cb + 1);
        float e0 = __ldg(beta + cb),  e1 = __ldg(beta + cb + 1);
#pragma unroll
        for (int mi = 0; mi < 2; mi++)
#pragma unroll
        for (int rh = 0; rh < 2; rh++) {
            int lr = wm * 32 + mi * 16 + g + rh * 8;
            if (lr < n_rows) {
                float y0 = (acc8[ch][mi][rh*2]   - mu[mi][rh]) * rs[mi][rh] * g0 + e0;
                float y1 = (acc8[ch][mi][rh*2+1] - mu[mi][rh]) * rs[mi][rh] * g1 + e1;
                *(float2*)(out + (size_t)(base + lr) * DDEC + cb) =
                    make_float2(tanh_fast(y0), tanh_fast(y1));
            }
        }
    }
}

// ---------------------------------------------------------------------------
// x_f precompute (FFMA, small): g_xf[r] = x[r] @ W_f + b_f  for r < NPAR
// ---------------------------------------------------------------------------
#define TS 68
__global__ void xf_kernel(const float* __restrict__ x, const float* __restrict__ W_f,
                          const float* __restrict__ b_f) {
    extern __shared__ float sm[];
    float* As = sm;
    float* Ws = sm + 128 * TS;
    int t = threadIdx.x;
    int base = blockIdx.x << 6;
    int n_rows = NPAR - base; if (n_rows > 64) n_rows = 64;
    int m0 = (t & 15) * 4, c0 = (t >> 4) * 4;

#pragma unroll
    for (int i = 0; i < 32; i++) {
        int idx = t + 256 * i;
        int m = idx >> 7, k = idx & 127;
        float v = 0.f;
        if (m < n_rows) v = x[(size_t)(base + m) * HH + k];
        As[k * TS + m] = v;
    }
    for (int ch = 0; ch < 2; ch++) {
        __syncthreads();
#pragma unroll
        for (int i = 0; i < 32; i++) {
            int idx = t + 256 * i;
            int k = idx >> 6, c = idx & 63;
            Ws[k * TS + c] = W_f[k * HH + ch * 64 + c];
        }
        __syncthreads();
        float acc[4][4] = {};
#pragma unroll 8
        for (int k = 0; k < 128; k++) {
            float4 a = *(const float4*)(As + k * TS + m0);
            float4 b = *(const float4*)(Ws + k * TS + c0);
            acc[0][0] += a.x*b.x; acc[0][1] += a.x*b.y; acc[0][2] += a.x*b.z; acc[0][3] += a.x*b.w;
            acc[1][0] += a.y*b.x; acc[1][1] += a.y*b.y; acc[1][2] += a.y*b.z; acc[1][3] += a.y*b.w;
            acc[2][0] += a.z*b.x; acc[2][1] += a.z*b.y; acc[2][2] += a.z*b.z; acc[2][3] += a.z*b.w;
            acc[3][0] += a.w*b.x; acc[3][1] += a.w*b.y; acc[3][2] += a.w*b.z; acc[3][3] += a.w*b.w;
        }
#pragma unroll
        for (int i = 0; i < 4; i++)
#pragma unroll
            for (int j = 0; j < 4; j++) {
                int m = m0 + i, cc = ch * 64 + c0 + j;
                if (m < n_rows)
                    g_xf[(size_t)(base + m) * HH + cc] = acc[i][j] + b_f[cc];
            }
    }
}

// ---------------------------------------------------------------------------
extern "C" void kernel_launch(void* const* d_in, const int* in_sizes, int n_in,
                              void* d_out, int out_size) {
    const float* x = (const float*)d_in[0];
    int wi = 3;
    if (n_in > 3 && in_sizes[3] <= 1) wi = 4;
    const float* W_iou = (const float*)d_in[wi + 0];
    const float* b_iou = (const float*)d_in[wi + 1];
    const float* U_iou = (const float*)d_in[wi + 2];
    const float* W_f   = (const float*)d_in[wi + 3];
    const float* b_f   = (const float*)d_in[wi + 4];
    const float* U_f   = (const float*)d_in[wi + 5];
    const float* W_out = (const float*)d_in[wi + 6];
    const float* b_out = (const float*)d_in[wi + 7];
    const float* gamma = (const float*)d_in[wi + 8];
    const float* beta  = (const float*)d_in[wi + 9];
    float* out = (float*)d_out;

    cudaFuncSetAttribute(level_mm, cudaFuncAttributeMaxDynamicSharedMemorySize, SM_LVL);
    cudaFuncSetAttribute(out_mm,   cudaFuncAttributeMaxDynamicSharedMemorySize, SM_OUT);
    cudaFuncSetAttribute(xf_kernel, cudaFuncAttributeMaxDynamicSharedMemorySize,
                         (2 * 128 * TS) * (int)sizeof(float));

    prep_all<<<576, 256>>>(W_iou, U_iou, U_f, W_out);
    xf_kernel<<<(NPAR + 63) / 64, 256, (2 * 128 * TS) * sizeof(float)>>>(x, W_f, b_f);

    const int off[8] = {0, 1, 9, 73, 585, 4681, 37449, 299593};
    for (int l = 6; l >= 0; l--) {
        int base = off[l], n = off[l + 1] - off[l];
        int blocks = (n + 127) / 128;
        level_mm<<<blocks, 256, SM_LVL>>>(x, b_iou, base, n,
                                          (l < 6) ? 1 : 0, (l > 0) ? 1 : 0);
    }
    out_mm<<<(NN + 63) / 64, 256, SM_OUT>>>(b_out, gamma, beta, out);
}

// round 17
// speedup vs baseline: 1.0707x; 1.0707x over previous
#include <cuda_runtime.h>
#include <cuda_fp16.h>
#include <math.h>
#include <stdint.h>

// ---------------------------------------------------------------------------
// Problem constants
// ---------------------------------------------------------------------------
#define NN    299593      // total nodes, complete 8-ary tree, 7 levels
#define HH    128         // D_ENC == D_EMB
#define NIOU  384         // 3*H
#define DDEC  256
#define NPAR  37449       // nodes at levels 0..5 (all parents)

#define CHUNK_BYTES 8192  // one pre-swizzled B chunk: 32 N-rows x 128 K x fp16
#define CHUNK_U4    (CHUNK_BYTES / 16)

// Scratch (device globals: allocation-free per harness rules)
__device__ float g_h [(size_t)NN  * HH];
__device__ float g_c [(size_t)NN  * HH];
__device__ float g_xf[(size_t)NPAR * HH];
__device__ float g_uh[(size_t)NPAR * NIOU];
__device__ float g_fc[(size_t)NPAR * HH];

// Pre-swizzled fp16 weight blobs (single-rounded), 32-row x 128-K chunks
__device__ uint4 g_Wiou_sw[12 * CHUNK_U4];
__device__ uint4 g_U_sw   [16 * CHUNK_U4];  // [U_iou(384) | U_f(128)] cols
__device__ uint4 g_Wout_sw[ 8 * CHUNK_U4];

// ---------------------------------------------------------------------------
// Helpers
// ---------------------------------------------------------------------------
__device__ __forceinline__ uint32_t smem_to_u32(const void* p) {
    uint32_t a;
    asm("{ .reg .u64 t; cvta.to.shared.u64 t, %1; cvt.u32.u64 %0, t; }" : "=r"(a) : "l"(p));
    return a;
}
__device__ __forceinline__ uint32_t swz(uint32_t o) { return o ^ ((o >> 3) & 0x70); }
__device__ __forceinline__ uint32_t offA(int row, int k) {   // 128-row tile: 16 atoms/kblk
    return swz((uint32_t)(((row >> 3) + (k >> 6) * 16) * 1024 + (row & 7) * 128 + (k & 63) * 2));
}
__device__ __forceinline__ uint32_t offA64(int row, int k) { // 64-row tile: 8 atoms/kblk
    return swz((uint32_t)(((row >> 3) + (k >> 6) * 8) * 1024 + (row & 7) * 128 + (k & 63) * 2));
}
__device__ __forceinline__ uint32_t offA16(int row, int k) { // 16-row tile: 2 atoms/kblk
    return swz((uint32_t)(((row >> 3) + (k >> 6) * 2) * 1024 + (row & 7) * 128 + (k & 63) * 2));
}
__device__ __forceinline__ uint32_t offB32(int row, int k) { // 32-row tile: 4 atoms/kblk
    return swz((uint32_t)(((row >> 3) + (k >> 6) * 4) * 1024 + (row & 7) * 128 + (k & 63) * 2));
}
__device__ __forceinline__ uint32_t packh2(float a, float b) {
    __half2 h = __floats2half2_rn(a, b);
    return *reinterpret_cast<uint32_t*>(&h);
}
__device__ __forceinline__ float sigf(float v) {
    return __fdividef(1.0f, 1.0f + __expf(-v));
}
__device__ __forceinline__ float tanh_fast(float x) {
    float t = __expf(2.0f * x);
    return 1.0f - __fdividef(2.0f, t + 1.0f);
}

#define LDSM4(R0, R1, R2, R3, ADDR) \
    asm volatile("ldmatrix.sync.aligned.m8n8.x4.shared.b16 {%0,%1,%2,%3}, [%4];" \
                 : "=r"(R0), "=r"(R1), "=r"(R2), "=r"(R3) : "r"(ADDR))
#define LDSM2(R0, R1, ADDR) \
    asm volatile("ldmatrix.sync.aligned.m8n8.x2.shared.b16 {%0,%1}, [%2];" \
                 : "=r"(R0), "=r"(R1) : "r"(ADDR))

__device__ __forceinline__ void mma_f16(float (&d)[4], const uint32_t (&a)[4],
                                        uint32_t b0, uint32_t b1) {
    asm volatile("mma.sync.aligned.m16n8k16.row.col.f32.f16.f16.f32 "
                 "{%0,%1,%2,%3}, {%4,%5,%6,%7}, {%8,%9}, {%0,%1,%2,%3};"
                 : "+f"(d[0]), "+f"(d[1]), "+f"(d[2]), "+f"(d[3])
                 : "r"(a[0]), "r"(a[1]), "r"(a[2]), "r"(a[3]), "r"(b0), "r"(b1));
}

__device__ __forceinline__ void zacc(float (&a)[2][2][4]) {
#pragma unroll
    for (int i = 0; i < 2; i++)
#pragma unroll
        for (int j = 0; j < 2; j++)
#pragma unroll
            for (int k = 0; k < 4; k++) a[i][j][k] = 0.f;
}

// Triple-fused pass: A fragments loaded ONCE per kstep feed 3 B chunks (I,O,U)
__device__ __forceinline__ void mma_trip32(uint32_t Abase, uint32_t B0, uint32_t B1,
                                           uint32_t B2,
                                           float (&aI)[2][2][4], float (&aO)[2][2][4],
                                           float (&aU)[2][2][4],
                                           int wm, int wn, int lane) {
    int rA = wm * 32 + (lane & 15);
    uint32_t PA = Abase + ((rA >> 3) << 10) + ((rA & 7) << 7);
    uint32_t CA = (rA & 7) << 4;
    int aK = (lane >> 4) << 3;
    int nB = wn * 16 + (((lane >> 4) & 1) << 3) + (lane & 7);
    uint32_t SB = ((uint32_t)(nB >> 3) << 10) + ((uint32_t)(nB & 7) << 7);
    uint32_t CB = (nB & 7) << 4;
    int bK = ((lane >> 3) & 1) << 3;
#pragma unroll
    for (int s = 0; s < 8; s++) {
        int kA = (s << 4) + aK;
        int kB = (s << 4) + bK;
        uint32_t aAh = PA + ((uint32_t)(kA >> 6) << 14) + ((uint32_t)((kA & 63) << 1) ^ CA);
        uint32_t ob  = SB + ((uint32_t)(kB >> 6) << 12) + ((uint32_t)((kB & 63) << 1) ^ CB);
        uint32_t ah0[4], ah1[4], bI[4], bO[4], bU[4];
        LDSM4(ah0[0], ah0[1], ah0[2], ah0[3], aAh);
        LDSM4(ah1[0], ah1[1], ah1[2], ah1[3], aAh + 2048);
        LDSM4(bI[0], bI[1], bI[2], bI[3], B0 + ob);
        LDSM4(bO[0], bO[1], bO[2], bO[3], B1 + ob);
        LDSM4(bU[0], bU[1], bU[2], bU[3], B2 + ob);
        mma_f16(aI[0][0], ah0, bI[0], bI[1]);
        mma_f16(aI[1][0], ah1, bI[0], bI[1]);
        mma_f16(aI[0][1], ah0, bI[2], bI[3]);
        mma_f16(aI[1][1], ah1, bI[2], bI[3]);
        mma_f16(aO[0][0], ah0, bO[0], bO[1]);
        mma_f16(aO[1][0], ah1, bO[0], bO[1]);
        mma_f16(aO[0][1], ah0, bO[2], bO[3]);
        mma_f16(aO[1][1], ah1, bO[2], bO[3]);
        mma_f16(aU[0][0], ah0, bU[0], bU[1]);
        mma_f16(aU[1][0], ah1, bU[0], bU[1]);
        mma_f16(aU[0][1], ah0, bU[2], bU[3]);
        mma_f16(aU[1][1], ah1, bU[2], bU[3]);
    }
}

// Pair-fused: A fragments feed 2 B chunks
__device__ __forceinline__ void mma_pair32(uint32_t Abase, uint32_t B0, uint32_t B1,
                                           float (&aX)[2][2][4], float (&aY)[2][2][4],
                                           int wm, int wn, int lane) {
    int rA = wm * 32 + (lane & 15);
    uint32_t PA = Abase + ((rA >> 3) << 10) + ((rA & 7) << 7);
    uint32_t CA = (rA & 7) << 4;
    int aK = (lane >> 4) << 3;
    int nB = wn * 16 + (((lane >> 4) & 1) << 3) + (lane & 7);
    uint32_t SB = ((uint32_t)(nB >> 3) << 10) + ((uint32_t)(nB & 7) << 7);
    uint32_t CB = (nB & 7) << 4;
    int bK = ((lane >> 3) & 1) << 3;
#pragma unroll
    for (int s = 0; s < 8; s++) {
        int kA = (s << 4) + aK;
        int kB = (s << 4) + bK;
        uint32_t aAh = PA + ((uint32_t)(kA >> 6) << 14) + ((uint32_t)((kA & 63) << 1) ^ CA);
        uint32_t ob  = SB + ((uint32_t)(kB >> 6) << 12) + ((uint32_t)((kB & 63) << 1) ^ CB);
        uint32_t ah0[4], ah1[4], bX[4], bY[4];
        LDSM4(ah0[0], ah0[1], ah0[2], ah0[3], aAh);
        LDSM4(ah1[0], ah1[1], ah1[2], ah1[3], aAh + 2048);
        LDSM4(bX[0], bX[1], bX[2], bX[3], B0 + ob);
        LDSM4(bY[0], bY[1], bY[2], bY[3], B1 + ob);
        mma_f16(aX[0][0], ah0, bX[0], bX[1]);
        mma_f16(aX[1][0], ah1, bX[0], bX[1]);
        mma_f16(aX[0][1], ah0, bX[2], bX[3]);
        mma_f16(aX[1][1], ah1, bX[2], bX[3]);
        mma_f16(aY[0][0], ah0, bY[0], bY[1]);
        mma_f16(aY[1][0], ah1, bY[0], bY[1]);
        mma_f16(aY[0][1], ah0, bY[2], bY[3]);
        mma_f16(aY[1][1], ah1, bY[2], bY[3]);
    }
}

// Out kernel: 64-row tile, 4 B chunks share A fragments; per-warp n8 per chunk
__device__ __forceinline__ void mma_quad64(uint32_t Abase, uint32_t Bbase,
                                           float (*acc)[2][4],   // [4][2][4]
                                           int wm, int wn, int lane) {
    int rA = wm * 32 + (lane & 15);
    uint32_t PA = Abase + ((rA >> 3) << 10) + ((rA & 7) << 7);
    uint32_t CA = (rA & 7) << 4;
    int aK = (lane >> 4) << 3;
    int nB = wn * 8 + (lane & 7);
    uint32_t SB = ((uint32_t)(nB >> 3) << 10) + ((uint32_t)(nB & 7) << 7);
    uint32_t CB = (nB & 7) << 4;
    int bK = ((lane >> 3) & 1) << 3;
#pragma unroll
    for (int s = 0; s < 8; s++) {
        int kA = (s << 4) + aK;
        int kB = (s << 4) + bK;
        uint32_t aAh = PA + ((uint32_t)(kA >> 6) << 13) + ((uint32_t)((kA & 63) << 1) ^ CA);
        uint32_t ob  = SB + ((uint32_t)(kB >> 6) << 12) + ((uint32_t)((kB & 63) << 1) ^ CB);
        uint32_t ah0[4], ah1[4];
        LDSM4(ah0[0], ah0[1], ah0[2], ah0[3], aAh);
        LDSM4(ah1[0], ah1[1], ah1[2], ah1[3], aAh + 2048);
#pragma unroll
        for (int j = 0; j < 4; j++) {
            uint32_t b0, b1;
            LDSM2(b0, b1, Bbase + (uint32_t)j * CHUNK_BYTES + ob);
            mma_f16(acc[j][0], ah0, b0, b1);
            mma_f16(acc[j][1], ah1, b0, b1);
        }
    }
}

// ---------------------------------------------------------------------------
// cp.async: one 8KB chunk, 256 threads x 2 x 16B, one commit group
// ---------------------------------------------------------------------------
__device__ __forceinline__ void cp_chunk(uint32_t dst, const uint4* src, int t) {
    const char* s = (const char*)src;
#pragma unroll
    for (int i = 0; i < 2; i++)
        asm volatile("cp.async.cg.shared.global [%0], [%1], 16;"
                     :: "r"(dst + (uint32_t)(t * 16 + i * 4096)),
                        "l"(s + t * 16 + i * 4096) : "memory");
    asm volatile("cp.async.commit_group;" ::: "memory");
}
#define CP_WAIT0() asm volatile("cp.async.wait_group 0;" ::: "memory")

// ---------------------------------------------------------------------------
// Weight prep (single launch): fp16 round + swizzle all four blobs
// ---------------------------------------------------------------------------
__global__ void prep_all(const float* __restrict__ W_iou, const float* __restrict__ U_iou,
                         const float* __restrict__ U_f, const float* __restrict__ W_out) {
    int b = blockIdx.x;
    const float* src; int ncols, dst_id, chunkoff, rel;
    if (b < 192)      { src = W_iou; ncols = 384; dst_id = 0; chunkoff = 0;  rel = b; }
    else if (b < 384) { src = U_iou; ncols = 384; dst_id = 1; chunkoff = 0;  rel = b - 192; }
    else if (b < 448) { src = U_f;   ncols = 128; dst_id = 1; chunkoff = 12; rel = b - 384; }
    else              { src = W_out; ncols = 256; dst_id = 2; chunkoff = 0;  rel = b - 448; }
    int idx = rel * 256 + threadIdx.x;
    if (idx >= 128 * ncols) return;
    int k = idx / ncols, n = idx - k * ncols;
    float v = src[k * ncols + n];
    unsigned short hu = __half_as_ushort(__float2half_rn(v));
    unsigned char* bb = (dst_id == 0) ? (unsigned char*)g_Wiou_sw
                      : (dst_id == 1) ? (unsigned char*)g_U_sw
                                      : (unsigned char*)g_Wout_sw;
    unsigned char* blob = bb + (size_t)(chunkoff + (n >> 5)) * CHUNK_BYTES;
    int row = n & 31;
    *(unsigned short*)(blob + offB32(row, k)) = hu;
}

// ---------------------------------------------------------------------------
// Level SMEM (occ 2): A [0,32768) | A2 [32768,36864) | ring 8x8KB [36864,102400)
// Out SMEM: A64 [0,16384) | ring 8x8KB [16384,81920) | part [81920,83968)
// ---------------------------------------------------------------------------
#define SM_A2    32768
#define SM_B     36864
#define SM_LVL   102400
#define SM_OB    16384
#define SM_OPART 81920
#define SM_OUT   83968

// build a 128x128 fp16 tile from fp32 rows (src row-major, HH cols)
__device__ __forceinline__ void build_tile(char* Ac, const float* src, size_t base,
                                           int n_rows, int t) {
    int row = t >> 1, kh = (t & 1) << 6;
    bool val = row < n_rows;
    const float4* xr = (const float4*)(src + (base + row) * HH + kh);
#pragma unroll
    for (int gg = 0; gg < 8; gg++) {
        float v[8];
        if (val) {
            float4 a = xr[gg * 2], b = xr[gg * 2 + 1];
            v[0]=a.x; v[1]=a.y; v[2]=a.z; v[3]=a.w; v[4]=b.x; v[5]=b.y; v[6]=b.z; v[7]=b.w;
        } else {
#pragma unroll
            for (int q = 0; q < 8; q++) v[q] = 0.f;
        }
        *(uint4*)(Ac + offA(row, kh + gg * 8)) =
            make_uint4(packh2(v[0], v[1]), packh2(v[2], v[3]),
                       packh2(v[4], v[5]), packh2(v[6], v[7]));
    }
}

// 64-row variant (4 threads per row, 32 K each)
__device__ __forceinline__ void build_tile64(char* Ac, const float* src, size_t base,
                                             int n_rows, int t) {
    int row = t >> 2, kh = (t & 3) << 5;
    bool val = row < n_rows;
    const float4* xr = (const float4*)(src + (base + row) * HH + kh);
#pragma unroll
    for (int gg = 0; gg < 4; gg++) {
        float v[8];
        if (val) {
            float4 a = xr[gg * 2], b = xr[gg * 2 + 1];
            v[0]=a.x; v[1]=a.y; v[2]=a.z; v[3]=a.w; v[4]=b.x; v[5]=b.y; v[6]=b.z; v[7]=b.w;
        } else {
#pragma unroll
            for (int q = 0; q < 8; q++) v[q] = 0.f;
        }
        *(uint4*)(Ac + offA64(row, kh + gg * 8)) =
            make_uint4(packh2(v[0], v[1]), packh2(v[2], v[3]),
                       packh2(v[4], v[5]), packh2(v[6], v[7]));
    }
}

// chunk c -> blob source (0..11 GEMM1 as (I_p,O_p,U_p) triples, 12..27 GEMM2)
__device__ __forceinline__ const uint4* lvl_src(int c) {
    if (c < 12) {
        int p = c / 3, sub = c - p * 3;              // blob chunk = sub*4 + p
        return g_Wiou_sw + (size_t)(sub * 4 + p) * CHUNK_U4;
    }
    return g_U_sw + (size_t)(c - 12) * CHUNK_U4;
}
// step s: s<4 -> GEMM1 pass s (3 chunks); s=4..6 -> GEMM2a (4 tiny); s=7 -> GEMM2b (4)
__device__ __forceinline__ int st_start(int s) { return (s < 4) ? 3 * s : 12 + 4 * (s - 4); }
__device__ __forceinline__ int st_cnt(int s)   { return (s < 4) ? 3 : 4; }
__device__ __forceinline__ void issue_group(uint32_t sb, int s, int t) {
    int st = st_start(s), cn = st_cnt(s);
    uint32_t slot = (uint32_t)((s & 1) * 4);
    for (int j = 0; j < cn; j++)
        cp_chunk(sb + SM_B + (slot + j) * CHUNK_BYTES, lvl_src(st + j), t);
}

// ---------------------------------------------------------------------------
// Fused per-level kernel: one CTA per 128-row tile, 256 threads, 2 CTAs/SM
// 8 steps: 4 GEMM1 passes (triple-fused + epilogue), 3 GEMM2a (8-warp), 1 GEMM2b
// ---------------------------------------------------------------------------
__global__ __launch_bounds__(256, 2)
void level_mm(const float* __restrict__ x, const float* __restrict__ b_iou,
              int base0, int n_total, int read_sums, int has_parent) {
    extern __shared__ __align__(1024) char smem[];
    uint32_t sb = smem_to_u32(smem);
    int t = threadIdx.x, lane = t & 31, w = t >> 5;
    int wm = w & 3, wn = w >> 2;
    int q = lane & 3, g = lane >> 2;
    int base = base0 + ((int)blockIdx.x << 7);
    int n_rows = n_total - ((int)blockIdx.x << 7); if (n_rows > 128) n_rows = 128;
    int pbase = (base - 1) >> 3;
    const int n_steps = has_parent ? 8 : 4;

    issue_group(sb, 0, t);
    build_tile(smem, x, (size_t)base, n_rows, t);

    float accI[2][2][4], accO[2][2][4], accU[2][2][4];
    zacc(accI); zacc(accO); zacc(accU);

    for (int s = 0; s < n_steps; s++) {
        CP_WAIT0();
        __syncthreads();               // group s landed; prior step's reads done
        if (s + 1 < n_steps) issue_group(sb, s + 1, t);
        uint32_t B0 = sb + SM_B + (uint32_t)((s & 1) * 4) * CHUNK_BYTES;

        if (s < 4) {
            int p = s;
            mma_trip32(sb, B0, B0 + CHUNK_BYTES, B0 + 2 * CHUNK_BYTES,
                       accI, accO, accU, wm, wn, lane);
            // epilogue for pass p: gates -> c,h (global) + A2 sibling sums
#pragma unroll
            for (int mi = 0; mi < 2; mi++)
#pragma unroll
            for (int nn = 0; nn < 2; nn++) {
                int cp = p * 32 + wn * 16 + nn * 8 + 2 * q;
                float bi0 = __ldg(b_iou + cp),       bi1 = __ldg(b_iou + cp + 1);
                float bo0 = __ldg(b_iou + 128 + cp), bo1 = __ldg(b_iou + 129 + cp);
                float bu0 = __ldg(b_iou + 256 + cp), bu1 = __ldg(b_iou + 257 + cp);
#pragma unroll
                for (int rh = 0; rh < 2; rh++) {
                    int lr = wm * 32 + mi * 16 + g + rh * 8;
                    int rg = base + lr;
                    bool val = lr < n_rows;
                    float2 ui = make_float2(0.f, 0.f), uo = ui, uu = ui, fc = ui;
                    if (val && read_sums) {
                        const float* uh = g_uh + (size_t)rg * NIOU + cp;
                        ui = *(const float2*)(uh);
                        uo = *(const float2*)(uh + 128);
                        uu = *(const float2*)(uh + 256);
                        fc = *(const float2*)(g_fc + (size_t)rg * HH + cp);
                    }
                    float c0 = sigf(accI[mi][nn][rh*2]   + bi0 + ui.x) *
                               tanh_fast(accU[mi][nn][rh*2]   + bu0 + uu.x) + fc.x;
                    float c1 = sigf(accI[mi][nn][rh*2+1] + bi1 + ui.y) *
                               tanh_fast(accU[mi][nn][rh*2+1] + bu1 + uu.y) + fc.y;
                    float h0 = sigf(accO[mi][nn][rh*2]   + bo0 + uo.x) * tanh_fast(c0);
                    float h1 = sigf(accO[mi][nn][rh*2+1] + bo1 + uo.y) * tanh_fast(c1);
                    if (val) {
                        *(float2*)(g_c + (size_t)rg * HH + cp) = make_float2(c0, c1);
                        *(float2*)(g_h + (size_t)rg * HH + cp) = make_float2(h0, h1);
                    }
                    if (has_parent) {
                        float hs0 = val ? h0 : 0.f, hs1 = val ? h1 : 0.f;
                        hs0 += __shfl_xor_sync(0xffffffffu, hs0, 4);
                        hs0 += __shfl_xor_sync(0xffffffffu, hs0, 8);
                        hs0 += __shfl_xor_sync(0xffffffffu, hs0, 16);
                        hs1 += __shfl_xor_sync(0xffffffffu, hs1, 4);
                        hs1 += __shfl_xor_sync(0xffffffffu, hs1, 8);
                        hs1 += __shfl_xor_sync(0xffffffffu, hs1, 16);
                        if (lane < 4) {
                            int row2 = 4 * wm + 2 * mi + rh;
                            *(uint32_t*)(smem + SM_A2 + offA16(row2, cp)) =
                                packh2(hs0, hs1);
                        }
                    }
                }
            }
            zacc(accI); zacc(accO); zacc(accU);
            if (s == 3 && has_parent) {
                __syncthreads();               // all warps done reading A (GEMM1)
                build_tile(smem, g_h, (size_t)base, n_rows, t);
            }
        } else if (s < 7) {
            // four tiny GEMM2a chunks across ALL 8 warps:
            // warp w -> chunk ch0 + (w>>1), n-half (w&1)*16 (m16n16 per warp)
            int ch = (st_start(s) - 12) + (w >> 1);
            uint32_t Bb = B0 + (uint32_t)(w >> 1) * CHUNK_BYTES;
            float acc2[2][4] = {{0.f,0.f,0.f,0.f},{0.f,0.f,0.f,0.f}};
            int rA2 = lane & 15;
            uint32_t PA2 = (sb + SM_A2) + ((uint32_t)(rA2 >> 3) << 10)
                                        + ((uint32_t)(rA2 & 7) << 7);
            uint32_t CA2 = (rA2 & 7) << 4;
            int aK = (lane >> 4) << 3;
            int nB2 = (w & 1) * 16 + (((lane >> 4) & 1) << 3) + (lane & 7);
            uint32_t PB2 = Bb + ((uint32_t)(nB2 >> 3) << 10)
                              + ((uint32_t)(nB2 & 7) << 7);
            uint32_t CB2 = (nB2 & 7) << 4;
            int kB2 = ((lane >> 3) & 1) << 3;
#pragma unroll
            for (int ks = 0; ks < 8; ks++) {
                int kA = (ks << 4) + aK;
                int kB = (ks << 4) + kB2;
                uint32_t aAh = PA2 + ((uint32_t)(kA >> 6) << 11)
                                   + (((uint32_t)(kA & 63) << 1) ^ CA2);
                uint32_t aB  = PB2 + ((uint32_t)(kB >> 6) << 12)
                                   + (((uint32_t)(kB & 63) << 1) ^ CB2);
                uint32_t a2h[4], b2[4];
                LDSM4(a2h[0], a2h[1], a2h[2], a2h[3], aAh);
                LDSM4(b2[0], b2[1], b2[2], b2[3], aB);
                mma_f16(acc2[0], a2h, b2[0], b2[1]);
                mma_f16(acc2[1], a2h, b2[2], b2[3]);
            }
#pragma unroll
            for (int nn = 0; nn < 2; nn++) {
                int cb2 = ch * 32 + (w & 1) * 16 + nn * 8 + 2 * (lane & 3);
                int gr0 = lane >> 2;
                if (gr0 * 8 < n_rows)
                    *(float2*)(g_uh + (size_t)(pbase + gr0) * NIOU + cb2) =
                        make_float2(acc2[nn][0], acc2[nn][1]);
                if ((gr0 + 8) * 8 < n_rows)
                    *(float2*)(g_uh + (size_t)(pbase + gr0 + 8) * NIOU + cb2) =
                        make_float2(acc2[nn][2], acc2[nn][3]);
            }
        } else {
            // GEMM2b: all 4 U_f chunks in this step, two pair-fused rounds
#pragma unroll
            for (int r = 0; r < 2; r++) {
                int cf0 = 2 * r;
                mma_pair32(sb, B0 + (uint32_t)(2 * r) * CHUNK_BYTES,
                           B0 + (uint32_t)(2 * r + 1) * CHUNK_BYTES,
                           accI, accO, wm, wn, lane);
#pragma unroll
                for (int jj = 0; jj < 2; jj++) {
#pragma unroll
                    for (int mi = 0; mi < 2; mi++)
#pragma unroll
                    for (int nn = 0; nn < 2; nn++) {
                        int cfl = (cf0 + jj) * 32 + wn * 16 + nn * 8 + 2 * q;
                        float v[4];
#pragma unroll
                        for (int rh = 0; rh < 2; rh++) {
                            int lr = wm * 32 + mi * 16 + g + rh * 8;
                            int rg = base + lr;
                            float a0 = jj ? accO[mi][nn][rh*2]   : accI[mi][nn][rh*2];
                            float a1 = jj ? accO[mi][nn][rh*2+1] : accI[mi][nn][rh*2+1];
                            if (lr < n_rows) {
                                int pr = (rg - 1) >> 3;
                                float2 xf2 = *(const float2*)(g_xf + (size_t)pr * HH + cfl);
                                float2 c2  = *(const float2*)(g_c  + (size_t)rg * HH + cfl);
                                v[rh*2]   = sigf(a0 + xf2.x) * c2.x;
                                v[rh*2+1] = sigf(a1 + xf2.y) * c2.y;
                            } else { v[rh*2] = 0.f; v[rh*2+1] = 0.f; }
                        }
#pragma unroll
                        for (int rr = 0; rr < 4; rr++) {
                            float sv = v[rr];
                            sv += __shfl_xor_sync(0xffffffffu, sv, 4);
                            sv += __shfl_xor_sync(0xffffffffu, sv, 8);
                            sv += __shfl_xor_sync(0xffffffffu, sv, 16);
                            v[rr] = sv;
                        }
                        if (lane < 4) {
#pragma unroll
                            for (int rh = 0; rh < 2; rh++) {
                                int lr0 = wm * 32 + mi * 16 + rh * 8;
                                if (lr0 < n_rows) {
                                    int pr = (base + lr0 - 1) >> 3;
                                    *(float2*)(g_fc + (size_t)pr * HH + cfl) =
                                        make_float2(v[rh*2], v[rh*2+1]);
                                }
                            }
                        }
                    }
                }
                zacc(accI); zacc(accO);
            }
        }
    }
}

// ---------------------------------------------------------------------------
// Output kernel: 64-row tiles, occupancy 2, 2 quad-fused steps
// ---------------------------------------------------------------------------
__global__ __launch_bounds__(256, 2)
void out_mm(const float* __restrict__ b_out, const float* __restrict__ gamma,
            const float* __restrict__ beta, float* __restrict__ out) {
    extern __shared__ __align__(1024) char smem[];
    uint32_t sb = smem_to_u32(smem);
    int t = threadIdx.x, lane = t & 31, w = t >> 5;
    int wm = w & 1, wn = w >> 1;           // 2 x 4 warp grid
    int q = lane & 3, g = lane >> 2;
    int base = (int)blockIdx.x << 6;
    int n_rows = NN - base; if (n_rows > 64) n_rows = 64;

#pragma unroll
    for (int j = 0; j < 4; j++)
        cp_chunk(sb + SM_OB + (uint32_t)j * CHUNK_BYTES, g_Wout_sw + (size_t)j * CHUNK_U4, t);

    build_tile64(smem, g_h, (size_t)base, n_rows, t);

    float acc8[8][2][4];
#pragma unroll
    for (int c = 0; c < 8; c++)
#pragma unroll
        for (int i = 0; i < 2; i++)
#pragma unroll
            for (int k = 0; k < 4; k++) acc8[c][i][k] = 0.f;

    for (int s = 0; s < 2; s++) {
        CP_WAIT0();
        __syncthreads();
        if (s == 0) {
#pragma unroll
            for (int j = 0; j < 4; j++)
                cp_chunk(sb + SM_OB + (uint32_t)(4 + j) * CHUNK_BYTES,
                         g_Wout_sw + (size_t)(4 + j) * CHUNK_U4, t);
        }
        mma_quad64(sb, sb + SM_OB + (uint32_t)(s * 4) * CHUNK_BYTES,
                   &acc8[4 * s], wm, wn, lane);
    }

    // bias + per-row partial sums
    float s2[2][2] = {{0.f,0.f},{0.f,0.f}}, sq[2][2] = {{0.f,0.f},{0.f,0.f}};
#pragma unroll
    for (int ch = 0; ch < 8; ch++) {
        int cb = ch * 32 + wn * 8 + 2 * q;
        float b0 = __ldg(b_out + cb), b1 = __ldg(b_out + cb + 1);
#pragma unroll
        for (int mi = 0; mi < 2; mi++)
#pragma unroll
        for (int rh = 0; rh < 2; rh++) {
            float y0 = (acc8[ch][mi][rh*2]   += b0);
            float y1 = (acc8[ch][mi][rh*2+1] += b1);
            s2[mi][rh] += y0 + y1;
            sq[mi][rh] += y0 * y0 + y1 * y1;
        }
    }
#pragma unroll
    for (int mi = 0; mi < 2; mi++)
#pragma unroll
    for (int rh = 0; rh < 2; rh++) {
        s2[mi][rh] += __shfl_xor_sync(0xffffffffu, s2[mi][rh], 1);
        s2[mi][rh] += __shfl_xor_sync(0xffffffffu, s2[mi][rh], 2);
        sq[mi][rh] += __shfl_xor_sync(0xffffffffu, sq[mi][rh], 1);
        sq[mi][rh] += __shfl_xor_sync(0xffffffffu, sq[mi][rh], 2);
    }
    float2* part = (float2*)(smem + SM_OPART);   // [64][4]
    __syncthreads();
    if (q == 0) {
#pragma unroll
        for (int mi = 0; mi < 2; mi++)
#pragma unroll
        for (int rh = 0; rh < 2; rh++) {
            int lr = wm * 32 + mi * 16 + g + rh * 8;
            part[lr * 4 + wn] = make_float2(s2[mi][rh], sq[mi][rh]);
        }
    }
    __syncthreads();
    float mu[2][2], rs[2][2];
#pragma unroll
    for (int mi = 0; mi < 2; mi++)
#pragma unroll
    for (int rh = 0; rh < 2; rh++) {
        int lr = wm * 32 + mi * 16 + g + rh * 8;
        float ssum = 0.f, qsum = 0.f;
#pragma unroll
        for (int j = 0; j < 4; j++) {
            float2 p = part[lr * 4 + j];
            ssum += p.x; qsum += p.y;
        }
        float m = ssum * (1.f / 256.f);
        float var = qsum * (1.f / 256.f) - m * m;
        mu[mi][rh] = m;
        rs[mi][rh] = rsqrtf(var + 1e-5f);
    }
#pragma unroll
    for (int ch = 0; ch < 8; ch++) {
        int cb = ch * 32 + wn * 8 + 2 * q;
        float g0 = __ldg(gamma + cb), g1 = __ldg(gamma + cb + 1);
        float e0 = __ldg(beta + cb),  e1 = __ldg(beta + cb + 1);
#pragma unroll
        for (int mi = 0; mi < 2; mi++)
#pragma unroll
        for (int rh = 0; rh < 2; rh++) {
            int lr = wm * 32 + mi * 16 + g + rh * 8;
            if (lr < n_rows) {
                float y0 = (acc8[ch][mi][rh*2]   - mu[mi][rh]) * rs[mi][rh] * g0 + e0;
                float y1 = (acc8[ch][mi][rh*2+1] - mu[mi][rh]) * rs[mi][rh] * g1 + e1;
                *(float2*)(out + (size_t)(base + lr) * DDEC + cb) =
                    make_float2(tanh_fast(y0), tanh_fast(y1));
            }
        }
    }
}

// ---------------------------------------------------------------------------
// x_f precompute (FFMA, small): g_xf[r] = x[r] @ W_f + b_f  for r < NPAR
// ---------------------------------------------------------------------------
#define TS 68
__global__ void xf_kernel(const float* __restrict__ x, const float* __restrict__ W_f,
                          const float* __restrict__ b_f) {
    extern __shared__ float sm[];
    float* As = sm;
    float* Ws = sm + 128 * TS;
    int t = threadIdx.x;
    int base = blockIdx.x << 6;
    int n_rows = NPAR - base; if (n_rows > 64) n_rows = 64;
    int m0 = (t & 15) * 4, c0 = (t >> 4) * 4;

#pragma unroll
    for (int i = 0; i < 32; i++) {
        int idx = t + 256 * i;
        int m = idx >> 7, k = idx & 127;
        float v = 0.f;
        if (m < n_rows) v = x[(size_t)(base + m) * HH + k];
        As[k * TS + m] = v;
    }
    for (int ch = 0; ch < 2; ch++) {
        __syncthreads();
#pragma unroll
        for (int i = 0; i < 32; i++) {
            int idx = t + 256 * i;
            int k = idx >> 6, c = idx & 63;
            Ws[k * TS + c] = W_f[k * HH + ch * 64 + c];
        }
        __syncthreads();
        float acc[4][4] = {};
#pragma unroll 8
        for (int k = 0; k < 128; k++) {
            float4 a = *(const float4*)(As + k * TS + m0);
            float4 b = *(const float4*)(Ws + k * TS + c0);
            acc[0][0] += a.x*b.x; acc[0][1] += a.x*b.y; acc[0][2] += a.x*b.z; acc[0][3] += a.x*b.w;
            acc[1][0] += a.y*b.x; acc[1][1] += a.y*b.y; acc[1][2] += a.y*b.z; acc[1][3] += a.y*b.w;
            acc[2][0] += a.z*b.x; acc[2][1] += a.z*b.y; acc[2][2] += a.z*b.z; acc[2][3] += a.z*b.w;
            acc[3][0] += a.w*b.x; acc[3][1] += a.w*b.y; acc[3][2] += a.w*b.z; acc[3][3] += a.w*b.w;
        }
#pragma unroll
        for (int i = 0; i < 4; i++)
#pragma unroll
            for (int j = 0; j < 4; j++) {
                int m = m0 + i, cc = ch * 64 + c0 + j;
                if (m < n_rows)
                    g_xf[(size_t)(base + m) * HH + cc] = acc[i][j] + b_f[cc];
            }
    }
}

// ---------------------------------------------------------------------------
extern "C" void kernel_launch(void* const* d_in, const int* in_sizes, int n_in,
                              void* d_out, int out_size) {
    const float* x = (const float*)d_in[0];
    int wi = 3;
    if (n_in > 3 && in_sizes[3] <= 1) wi = 4;
    const float* W_iou = (const float*)d_in[wi + 0];
    const float* b_iou = (const float*)d_in[wi + 1];
    const float* U_iou = (const float*)d_in[wi + 2];
    const float* W_f   = (const float*)d_in[wi + 3];
    const float* b_f   = (const float*)d_in[wi + 4];
    const float* U_f   = (const float*)d_in[wi + 5];
    const float* W_out = (const float*)d_in[wi + 6];
    const float* b_out = (const float*)d_in[wi + 7];
    const float* gamma = (const float*)d_in[wi + 8];
    const float* beta  = (const float*)d_in[wi + 9];
    float* out = (float*)d_out;

    cudaFuncSetAttribute(level_mm, cudaFuncAttributeMaxDynamicSharedMemorySize, SM_LVL);
    cudaFuncSetAttribute(out_mm,   cudaFuncAttributeMaxDynamicSharedMemorySize, SM_OUT);
    cudaFuncSetAttribute(xf_kernel, cudaFuncAttributeMaxDynamicSharedMemorySize,
                         (2 * 128 * TS) * (int)sizeof(float));

    prep_all<<<576, 256>>>(W_iou, U_iou, U_f, W_out);
    xf_kernel<<<(NPAR + 63) / 64, 256, (2 * 128 * TS) * sizeof(float)>>>(x, W_f, b_f);

    const int off[8] = {0, 1, 9, 73, 585, 4681, 37449, 299593};
    for (int l = 6; l >= 0; l--) {
        int base = off[l], n = off[l + 1] - off[l];
        int blocks = (n + 127) / 128;
        level_mm<<<blocks, 256, SM_LVL>>>(x, b_iou, base, n,
                                          (l < 6) ? 1 : 0, (l > 0) ? 1 : 0);
    }
    out_mm<<<(NN + 63) / 64, 256, SM_OUT>>>(b_out, gamma, beta, out);
}